// round 12
// baseline (speedup 1.0000x reference)
#include <cuda_runtime.h>
#include <cstdint>

#define PNUM 128
#define MAXBATCH 8192

typedef unsigned long long u64;

// ---- packed f32x2 helpers (sm_103a), all 2-source forms (RF-bank rt=2) ----
__device__ __forceinline__ u64 pk_add(u64 a, u64 b) {
    u64 r;
    asm("add.rn.f32x2 %0, %1, %2;" : "=l"(r) : "l"(a), "l"(b));
    return r;
}
__device__ __forceinline__ u64 pk_fma_sq(u64 x, u64 acc) {   // acc += x*x
    u64 r;
    asm("fma.rn.f32x2 %0, %1, %1, %2;" : "=l"(r) : "l"(x), "l"(acc));
    return r;
}
__device__ __forceinline__ u64 pk_pack(float lo, float hi) {
    u64 r;
    asm("mov.b64 %0, {%1, %2};" : "=l"(r) : "f"(lo), "f"(hi));
    return r;
}
__device__ __forceinline__ void pk_unpack(u64 v, float& lo, float& hi) {
    asm("mov.b64 {%0, %1}, %2;" : "=f"(lo), "=f"(hi) : "l"(v));
}

#define NEGMASK 0x8000000080000000ULL   // flip signs of both packed floats
#define KNEG1   0xBF800000BF800000ULL   // packed (-1.0f, -1.0f)

// Padded ring addressing: +2 u64 of pad per 8 u64. Lane window bases stride
// 10 u64 (80B) -> 16B-chunk index 5l mod 8 cycles all bank groups:
// conflict-free LDS.128. Pairs (a, a+1) with a even never straddle a pad
// (a mod 8 in {0,2,4,6}) and padded address stays even -> 16B aligned.
#define RING_PAD(a) ((a) + 2 * ((a) >> 3))
#define RING_SIZE (RING_PAD(256) + 4)   // guard pair at a=256,257

// smoothL1(d) = 0.5*d^2 - 0.5*(m-1)^2,  m = max(|d|, 1)
// fma pipe: FADD2(d), FFMA2(Q+=d*d), FADD2(r=m-1), FFMA2(R+=r*r)  (all rt=2)
// alu pipe: 2x FMNMX m,|d|,1.0 (abs = free src modifier)
__device__ __forceinline__ void evalpair(u64 p, u64 ng, u64& sQ, u64& sR) {
    u64 d = pk_add(p, ng);
    sQ = pk_fma_sq(d, sQ);
    float dx, dy;
    pk_unpack(d, dx, dy);
    float mx = fmaxf(fabsf(dx), 1.0f);
    float my = fmaxf(fabsf(dy), 1.0f);
    u64 m = pk_pack(mx, my);
    u64 r = pk_add(m, KNEG1);           // r = m - 1  (2-src packed)
    sR = pk_fma_sq(r, sR);
}

// Cap regs at 51 (20 blocks/SM = 40 warps, ~62% occ). Live set is ~50 regs,
// so this should be spill-free while closing the warp-starvation issue gaps
// seen at occ 48.8%.
__global__ __launch_bounds__(64, 20)
void match_kernel(const float* __restrict__ pred0,
                  const float* __restrict__ pred1,
                  const float* __restrict__ gt,
                  float* __restrict__ out,
                  float scale) {              // 0.5 / nbatch
    __shared__ __align__(16) u64 sp[2][PNUM];
    __shared__ __align__(16) u64 ring[RING_SIZE];   // negated gt, padded dup ring
    __shared__ float red[2];

    const int tid = threadIdx.x;        // 64 threads
    const int b = blockIdx.x;
    const int base = b * PNUM;

    // Prologue: thread t loads point pairs (2t, 2t+1) of each input.
    {
        const u64* p0 = reinterpret_cast<const u64*>(pred0) + base;
        const u64* p1 = reinterpret_cast<const u64*>(pred1) + base;
        const u64* pg = reinterpret_cast<const u64*>(gt) + base;
        ulonglong2 a0v = *reinterpret_cast<const ulonglong2*>(&p0[2 * tid]);
        ulonglong2 a1v = *reinterpret_cast<const ulonglong2*>(&p1[2 * tid]);
        ulonglong2 g   = *reinterpret_cast<const ulonglong2*>(&pg[2 * tid]);
        *reinterpret_cast<ulonglong2*>(&sp[0][2 * tid]) = a0v;
        *reinterpret_cast<ulonglong2*>(&sp[1][2 * tid]) = a1v;
        ulonglong2 ng = make_ulonglong2(g.x ^ NEGMASK, g.y ^ NEGMASK);
        *reinterpret_cast<ulonglong2*>(&ring[RING_PAD(2 * tid)]) = ng;
        *reinterpret_cast<ulonglong2*>(&ring[RING_PAD(2 * tid + 128)]) = ng;
        if (tid == 0)   // guard pair a=256,257 = ng[0],ng[1]
            *reinterpret_cast<ulonglong2*>(&ring[RING_PAD(256)]) = ng;
    }
    __syncthreads();

    // Warp w handles pred w; lane l handles shifts 4l..4l+3.
    const int l = tid & 31;
    const int w = tid >> 5;
    const u64* spw = sp[w];
    const int a0 = 4 * l;

    // Register window: 4 ring pairs, rotation period 4 (matches unroll 4 ->
    // no loop-carried register permutation).
    ulonglong2 C0 = *reinterpret_cast<const ulonglong2*>(&ring[RING_PAD(a0 + 0)]);
    ulonglong2 C1 = *reinterpret_cast<const ulonglong2*>(&ring[RING_PAD(a0 + 2)]);
    ulonglong2 C2 = *reinterpret_cast<const ulonglong2*>(&ring[RING_PAD(a0 + 4)]);
    ulonglong2 C3;

    u64 Q0 = 0, R0 = 0, Q1 = 0, R1 = 0, Q2 = 0, R2 = 0, Q3 = 0, R3 = 0;

    // Step s covers i = 2s, 2s+1 for all 4 shifts.
#define STEP(Ca, Cb, Cc, Cd, s)                                                   \
    {                                                                             \
        ulonglong2 P = *reinterpret_cast<const ulonglong2*>(&spw[2 * (s)]);       \
        Cd = *reinterpret_cast<const ulonglong2*>(&ring[RING_PAD(a0 + 2*(s) + 6)]); \
        evalpair(P.x, Ca.x, Q0, R0); evalpair(P.y, Ca.y, Q0, R0);                 \
        evalpair(P.x, Ca.y, Q1, R1); evalpair(P.y, Cb.x, Q1, R1);                 \
        evalpair(P.x, Cb.x, Q2, R2); evalpair(P.y, Cb.y, Q2, R2);                 \
        evalpair(P.x, Cb.y, Q3, R3); evalpair(P.y, Cc.x, Q3, R3);                 \
    }

#pragma unroll 4
    for (int su = 0; su < 16; su++) {
        const int s = 4 * su;
        STEP(C0, C1, C2, C3, s + 0)
        STEP(C1, C2, C3, C0, s + 1)
        STEP(C2, C3, C0, C1, s + 2)
        STEP(C3, C0, C1, C2, s + 3)
    }
#undef STEP

    // dis_j = (Qsum - Rsum) * 0.5 / 128
    float qx, qy, rx, ry;
    pk_unpack(Q0, qx, qy); pk_unpack(R0, rx, ry);
    float d0 = (qx + qy) - (rx + ry);
    pk_unpack(Q1, qx, qy); pk_unpack(R1, rx, ry);
    float d1 = (qx + qy) - (rx + ry);
    pk_unpack(Q2, qx, qy); pk_unpack(R2, rx, ry);
    float d2 = (qx + qy) - (rx + ry);
    pk_unpack(Q3, qx, qy); pk_unpack(R3, rx, ry);
    float d3 = (qx + qy) - (rx + ry);
    float dis = fminf(fminf(d0, d1), fminf(d2, d3)) * (0.5f / PNUM);

#pragma unroll
    for (int o = 16; o > 0; o >>= 1)
        dis = fminf(dis, __shfl_xor_sync(0xffffffffu, dis, o));
    if (l == 0)
        red[w] = dis;
    __syncthreads();
    // One pre-scaled float atomic per block into the final output; fp32 sum
    // nondeterminism over 8192 terms is ~1e-5 rel, far inside the 1e-3 gate.
    if (tid == 0)
        atomicAdd(out, (red[0] + red[1]) * scale);
}

extern "C" void kernel_launch(void* const* d_in, const int* in_sizes, int n_in,
                              void* d_out, int out_size) {
    const float* pred0 = (const float*)d_in[0];
    const float* pred1 = (const float*)d_in[1];
    const float* gt    = (const float*)d_in[2];
    int nbatch = in_sizes[0] / (PNUM * 2);
    if (nbatch > MAXBATCH) nbatch = MAXBATCH;

    // d_out is poisoned 0xAA by the harness; zero it (graph memset node).
    cudaMemsetAsync(d_out, 0, sizeof(float));
    match_kernel<<<nbatch, 64>>>(pred0, pred1, gt, (float*)d_out,
                                 0.5f / (float)nbatch);
}